// round 1
// baseline (speedup 1.0000x reference)
#include <cuda_runtime.h>
#include <cstdint>

#define DIM 128
#define N_NODES_MAX 100000

// Scratch for h = x@W + b (allocation-free rule: __device__ global)
__device__ float g_h[(size_t)N_NODES_MAX * DIM];

// ---------------------------------------------------------------------------
// GEMM: h[r][c] = sum_k x[r][k] * W[k][c] + b[c]
// Block: 256 threads, 32 rows per block.
// smem: W (128x128 f32 = 64KB) + x tile (32x128 f32 = 16KB) = 80KB dynamic.
// Thread (tx): lane = tx&31 -> float4 column group c4 = lane (cols 4*lane..4*lane+3)
//              wr  = tx>>5 -> rows wr*4 .. wr*4+3
// Each thread: 4 rows x 4 cols register tile, 16 FMA per k-step.
// ---------------------------------------------------------------------------
__global__ void __launch_bounds__(256) gemm_bias_kernel(
    const float* __restrict__ x, const float* __restrict__ W,
    const float* __restrict__ b, int n_rows)
{
    extern __shared__ float smem[];
    float*  sW  = smem;              // 128*128 floats
    float*  sX  = smem + DIM * DIM;  // 32*128 floats
    float4* sW4 = (float4*)sW;
    float4* sX4 = (float4*)sX;

    const int tx   = threadIdx.x;
    const int row0 = blockIdx.x * 32;

    // Load W: 4096 float4, 256 threads x 16
    const float4* W4 = (const float4*)W;
    #pragma unroll
    for (int i = 0; i < 16; i++) sW4[tx + 256 * i] = W4[tx + 256 * i];

    // Load x tile: 32 rows x 32 float4 = 1024 float4, 256 threads x 4
    const int rows_here = min(32, n_rows - row0);
    const float4* X4 = (const float4*)(x + (size_t)row0 * DIM);
    #pragma unroll
    for (int i = 0; i < 4; i++) {
        int idx = tx + 256 * i;
        if (idx < rows_here * 32) sX4[idx] = X4[idx];
    }
    __syncthreads();

    const int lane = tx & 31;   // float4 column index
    const int r0   = (tx >> 5) * 4;

    float4 bv = ((const float4*)b)[lane];
    float4 acc0 = bv, acc1 = bv, acc2 = bv, acc3 = bv;

    #pragma unroll 8
    for (int k = 0; k < DIM; k++) {
        float4 w = sW4[k * 32 + lane];
        float x0 = sX[(r0 + 0) * DIM + k];   // warp-broadcast LDS
        float x1 = sX[(r0 + 1) * DIM + k];
        float x2 = sX[(r0 + 2) * DIM + k];
        float x3 = sX[(r0 + 3) * DIM + k];
        acc0.x += x0 * w.x; acc0.y += x0 * w.y; acc0.z += x0 * w.z; acc0.w += x0 * w.w;
        acc1.x += x1 * w.x; acc1.y += x1 * w.y; acc1.z += x1 * w.z; acc1.w += x1 * w.w;
        acc2.x += x2 * w.x; acc2.y += x2 * w.y; acc2.z += x2 * w.z; acc2.w += x2 * w.w;
        acc3.x += x3 * w.x; acc3.y += x3 * w.y; acc3.z += x3 * w.z; acc3.w += x3 * w.w;
    }

    float4* H4 = (float4*)(g_h + (size_t)row0 * DIM);
    if (r0 + 0 < rows_here) H4[(r0 + 0) * 32 + lane] = acc0;
    if (r0 + 1 < rows_here) H4[(r0 + 1) * 32 + lane] = acc1;
    if (r0 + 2 < rows_here) H4[(r0 + 2) * 32 + lane] = acc2;
    if (r0 + 3 < rows_here) H4[(r0 + 3) * 32 + lane] = acc3;
}

// ---------------------------------------------------------------------------
// Zero the output (harness poisons d_out with 0xAA)
// ---------------------------------------------------------------------------
__global__ void __launch_bounds__(256) zero_kernel(float4* __restrict__ out, int n4)
{
    int i = blockIdx.x * blockDim.x + threadIdx.x;
    if (i < n4) out[i] = make_float4(0.f, 0.f, 0.f, 0.f);
}

// ---------------------------------------------------------------------------
// Scatter: out[rows[e]] += vals[e] * h[cols[e]]
// One warp per edge. Lane handles one float4 (4 columns): coalesced 512B
// gather from h, vectorized red.global.add.v4.f32 into out.
// ---------------------------------------------------------------------------
__global__ void __launch_bounds__(256) scatter_kernel(
    const float* __restrict__ vals,
    const int*   __restrict__ rows,
    const int*   __restrict__ cols,
    float*       __restrict__ out,
    int n_edges)
{
    int gid  = blockIdx.x * blockDim.x + threadIdx.x;
    int e    = gid >> 5;
    int lane = gid & 31;
    if (e >= n_edges) return;

    int   r = __ldg(rows + e);   // warp-uniform broadcast loads
    int   c = __ldg(cols + e);
    float v = __ldg(vals + e);

    float4 m = __ldg((const float4*)(g_h + (size_t)c * DIM) + lane);
    m.x *= v; m.y *= v; m.z *= v; m.w *= v;

    float* dst = out + (size_t)r * DIM + lane * 4;
    asm volatile("red.global.add.v4.f32 [%0], {%1, %2, %3, %4};"
                 :: "l"(dst), "f"(m.x), "f"(m.y), "f"(m.z), "f"(m.w)
                 : "memory");
}

// ---------------------------------------------------------------------------
// Launch
// Inputs (metadata order): x[N*128] f32, W[128*128] f32, b[128] f32,
//                          vals[E] f32, rows[E] i32, cols[E] i32
// Output: out[N*128] f32
// ---------------------------------------------------------------------------
extern "C" void kernel_launch(void* const* d_in, const int* in_sizes, int n_in,
                              void* d_out, int out_size)
{
    const float* x    = (const float*)d_in[0];
    const float* W    = (const float*)d_in[1];
    const float* b    = (const float*)d_in[2];
    const float* vals = (const float*)d_in[3];
    const int*   rows = (const int*)d_in[4];
    const int*   cols = (const int*)d_in[5];
    float*       out  = (float*)d_out;

    const int n_nodes = in_sizes[0] / DIM;
    const int n_edges = in_sizes[3];

    // 80KB dynamic smem for the GEMM kernel (W 64KB + x tile 16KB)
    static bool attr_set = false;
    const int smem_bytes = (DIM * DIM + 32 * DIM) * (int)sizeof(float);
    if (!attr_set) {
        cudaFuncSetAttribute(gemm_bias_kernel,
                             cudaFuncAttributeMaxDynamicSharedMemorySize, smem_bytes);
        attr_set = true;
    }

    // 1) zero output
    {
        int n4 = out_size / 4;
        int blocks = (n4 + 255) / 256;
        zero_kernel<<<blocks, 256>>>((float4*)out, n4);
    }

    // 2) h = x@W + b
    {
        int blocks = (n_nodes + 31) / 32;
        gemm_bias_kernel<<<blocks, 256, smem_bytes>>>(x, W, b, n_nodes);
    }

    // 3) scatter-aggregate (one warp per edge)
    {
        long long total_threads = (long long)n_edges * 32;
        int blocks = (int)((total_threads + 255) / 256);
        scatter_kernel<<<blocks, 256>>>(vals, rows, cols, out, n_edges);
    }
}

// round 2
// speedup vs baseline: 1.0463x; 1.0463x over previous
#include <cuda_runtime.h>
#include <cstdint>

#define DIM 128
#define N_NODES_MAX 100000

// Scratch for h = x@W + b (allocation-free rule: __device__ global)
__device__ float g_h[(size_t)N_NODES_MAX * DIM];

// Packed fp32 FMA: d.lo += a.lo*b.lo ; d.hi += a.hi*b.hi  (SASS FFMA2, PTX-only)
__device__ __forceinline__ void ffma2(uint64_t& d, uint64_t a, uint64_t b) {
    asm("fma.rn.f32x2 %0, %1, %2, %0;" : "+l"(d) : "l"(a), "l"(b));
}

// ---------------------------------------------------------------------------
// GEMM: h = x @ W + b using fma.rn.f32x2, K-paired accumulators.
//   Block: 256 threads, tile 64 rows x 128 cols.
//   Thread: rg = tx>>5 (8 row-groups, 8 rows each: r0=rg*8)
//           cg = tx&31, cols c = cg + 32*j, j=0..3
//   smem: sWT = W transposed [c][k], stride 130 floats (8B-aligned, low-conflict)
//         sX  = x tile row-major [64][128]
//   Inner loop per k-pair: 4 LDS.64 (W pairs) + 8 LDS.64 (x pairs) + 32 FFMA2.
//   Epilogue: acc.lo + acc.hi + b[c].
// ---------------------------------------------------------------------------
#define SWT_STRIDE 130                       // floats per transposed-W column
#define SWT_FLOATS (DIM * SWT_STRIDE)        // 16640
#define SX_FLOATS  (64 * DIM)                // 8192
#define GEMM_SMEM  ((SWT_FLOATS + SX_FLOATS) * 4)  // 99328 B

__global__ void __launch_bounds__(256, 2) gemm_bias_kernel(
    const float* __restrict__ x, const float* __restrict__ W,
    const float* __restrict__ b, int n_rows)
{
    extern __shared__ float smem[];
    float* sWT = smem;                 // [128 c][130] holds W[k][c] at sWT[c*130+k]
    float* sX  = smem + SWT_FLOATS;    // [64 r][128 k]

    const int tx   = threadIdx.x;
    const int row0 = blockIdx.x * 64;
    const int rows_here = min(64, n_rows - row0);

    // --- Load + transpose W (scalar: lanes along c -> coalesced LDG, 2-way STS) ---
    #pragma unroll
    for (int i = 0; i < 64; i++) {
        int idx = tx + 256 * i;        // 16384 scalars
        int k = idx >> 7;
        int c = idx & 127;
        sWT[c * SWT_STRIDE + k] = W[k * DIM + c];
    }

    // --- Load x tile row-major (float4 copy, zero-fill OOB rows) ---
    {
        const float4* X4 = (const float4*)(x + (size_t)row0 * DIM);
        float4* sX4 = (float4*)sX;
        #pragma unroll
        for (int i = 0; i < 8; i++) {
            int idx = tx + 256 * i;    // 2048 float4 = 64 rows x 32
            int r = idx >> 5;
            float4 v = make_float4(0.f, 0.f, 0.f, 0.f);
            if (r < rows_here) v = X4[idx];
            sX4[idx] = v;
        }
    }
    __syncthreads();

    const int cg = tx & 31;
    const int r0 = (tx >> 5) * 8;

    const uint64_t* sXp = (const uint64_t*)sX;   // (r, kp) at r*64 + kp
    const uint64_t* sWp = (const uint64_t*)sWT;  // (c, kp) at c*65 + kp

    uint64_t acc[8][4];
    #pragma unroll
    for (int i = 0; i < 8; i++)
        #pragma unroll
        for (int j = 0; j < 4; j++) acc[i][j] = 0ull;

    const uint64_t* w0p = sWp + (cg +  0) * 65;
    const uint64_t* w1p = sWp + (cg + 32) * 65;
    const uint64_t* w2p = sWp + (cg + 64) * 65;
    const uint64_t* w3p = sWp + (cg + 96) * 65;
    const uint64_t* xp  = sXp + r0 * 64;

    #pragma unroll 4
    for (int kp = 0; kp < 64; kp++) {
        uint64_t w0 = w0p[kp];
        uint64_t w1 = w1p[kp];
        uint64_t w2 = w2p[kp];
        uint64_t w3 = w3p[kp];
        #pragma unroll
        for (int i = 0; i < 8; i++) {
            uint64_t xv = xp[i * 64 + kp];
            ffma2(acc[i][0], xv, w0);
            ffma2(acc[i][1], xv, w1);
            ffma2(acc[i][2], xv, w2);
            ffma2(acc[i][3], xv, w3);
        }
    }

    // --- Epilogue: reduce pairs, add bias, store (coalesced over cg) ---
    float bj[4];
    #pragma unroll
    for (int j = 0; j < 4; j++) bj[j] = __ldg(b + cg + 32 * j);

    #pragma unroll
    for (int i = 0; i < 8; i++) {
        int r = r0 + i;
        if (r < rows_here) {
            float* hrow = g_h + (size_t)(row0 + r) * DIM;
            #pragma unroll
            for (int j = 0; j < 4; j++) {
                float2 p = *(float2*)&acc[i][j];
                hrow[cg + 32 * j] = p.x + p.y + bj[j];
            }
        }
    }
}

// ---------------------------------------------------------------------------
// Zero the output (harness poisons d_out with 0xAA)
// ---------------------------------------------------------------------------
__global__ void __launch_bounds__(256) zero_kernel(float4* __restrict__ out, int n4)
{
    int i = blockIdx.x * blockDim.x + threadIdx.x;
    if (i < n4) out[i] = make_float4(0.f, 0.f, 0.f, 0.f);
}

// ---------------------------------------------------------------------------
// Scatter: out[rows[e]] += vals[e] * h[cols[e]]
// One warp per edge; lane = one float4 column slice. Coalesced 512B gather
// from g_h, vectorized red.global.add.v4.f32 into out.
// ---------------------------------------------------------------------------
__global__ void __launch_bounds__(256) scatter_kernel(
    const float* __restrict__ vals,
    const int*   __restrict__ rows,
    const int*   __restrict__ cols,
    float*       __restrict__ out,
    int n_edges)
{
    int gid  = blockIdx.x * blockDim.x + threadIdx.x;
    int e    = gid >> 5;
    int lane = gid & 31;
    if (e >= n_edges) return;

    int   r = __ldg(rows + e);
    int   c = __ldg(cols + e);
    float v = __ldg(vals + e);

    float4 m = __ldg((const float4*)(g_h + (size_t)c * DIM) + lane);
    m.x *= v; m.y *= v; m.z *= v; m.w *= v;

    float* dst = out + (size_t)r * DIM + lane * 4;
    asm volatile("red.global.add.v4.f32 [%0], {%1, %2, %3, %4};"
                 :: "l"(dst), "f"(m.x), "f"(m.y), "f"(m.z), "f"(m.w)
                 : "memory");
}

// ---------------------------------------------------------------------------
// Launch
// Inputs (metadata order): x[N*128] f32, W[128*128] f32, b[128] f32,
//                          vals[E] f32, rows[E] i32, cols[E] i32
// ---------------------------------------------------------------------------
extern "C" void kernel_launch(void* const* d_in, const int* in_sizes, int n_in,
                              void* d_out, int out_size)
{
    const float* x    = (const float*)d_in[0];
    const float* W    = (const float*)d_in[1];
    const float* b    = (const float*)d_in[2];
    const float* vals = (const float*)d_in[3];
    const int*   rows = (const int*)d_in[4];
    const int*   cols = (const int*)d_in[5];
    float*       out  = (float*)d_out;

    const int n_nodes = in_sizes[0] / DIM;
    const int n_edges = in_sizes[3];

    static bool attr_set = false;
    if (!attr_set) {
        cudaFuncSetAttribute(gemm_bias_kernel,
                             cudaFuncAttributeMaxDynamicSharedMemorySize, GEMM_SMEM);
        attr_set = true;
    }

    // 1) zero output
    {
        int n4 = out_size / 4;
        int blocks = (n4 + 255) / 256;
        zero_kernel<<<blocks, 256>>>((float4*)out, n4);
    }

    // 2) h = x@W + b
    {
        int blocks = (n_nodes + 63) / 64;
        gemm_bias_kernel<<<blocks, 256, GEMM_SMEM>>>(x, W, b, n_nodes);
    }

    // 3) scatter-aggregate (one warp per edge)
    {
        long long total_threads = (long long)n_edges * 32;
        int blocks = (int)((total_threads + 255) / 256);
        scatter_kernel<<<blocks, 256>>>(vals, rows, cols, out, n_edges);
    }
}

// round 3
// speedup vs baseline: 1.7457x; 1.6685x over previous
#include <cuda_runtime.h>
#include <cstdint>

#define DIM  128
#define NMAX 100000
#define EMAX 1600000

// ---- scratch (__device__ globals: allocation-free rule) ----
__device__ float g_h[(size_t)NMAX * DIM];      // h = x@W + b
__device__ uint2 g_edges[EMAX];                // row-sorted (col, val_bits)
__device__ int   g_hist[NMAX];
__device__ int   g_offsets[NMAX + 1];
__device__ int   g_cursor[NMAX];
__device__ int   g_partials[1024];

// Packed fp32 FMA (SASS FFMA2 — PTX-only form)
__device__ __forceinline__ void ffma2(uint64_t& d, uint64_t a, uint64_t b) {
    asm("fma.rn.f32x2 %0, %1, %2, %0;" : "+l"(d) : "l"(a), "l"(b));
}
__device__ __forceinline__ uint64_t dup2(float v) {
    uint64_t d; asm("mov.b64 %0, {%1, %1};" : "=l"(d) : "f"(v)); return d;
}

// ---------------------------------------------------------------------------
// GEMM: h = x@W + b. W kept ROW-MAJOR in smem (no transpose, conflict-free
// float4 copy). Accumulators paired across columns: b-pair (W[k][c],W[k][c+1])
// is a native LDS.64; x scalar is warp-broadcast + mov.b64 dup.
// Block 256 thr, tile 64 rows x 128 cols; thread: 8 rows x 2 col-pairs.
// ---------------------------------------------------------------------------
#define GEMM_SMEM ((DIM * DIM + 64 * DIM) * 4)   // 96 KB

__global__ void __launch_bounds__(256, 2) gemm_bias_kernel(
    const float* __restrict__ x, const float* __restrict__ W,
    const float* __restrict__ b, int n_rows)
{
    extern __shared__ float smem[];
    float* sW = smem;            // [128][128] row-major
    float* sX = smem + DIM * DIM; // [64][128] row-major

    const int tx   = threadIdx.x;
    const int row0 = blockIdx.x * 64;
    const int rows_here = min(64, n_rows - row0);

    // W: straight float4 copy (coalesced, conflict-free)
    {
        const float4* W4 = (const float4*)W;
        float4* sW4 = (float4*)sW;
        #pragma unroll
        for (int i = 0; i < 16; i++) sW4[tx + 256 * i] = W4[tx + 256 * i];
    }
    // x tile: float4 copy, zero-fill OOB rows
    {
        const float4* X4 = (const float4*)(x + (size_t)row0 * DIM);
        float4* sX4 = (float4*)sX;
        #pragma unroll
        for (int i = 0; i < 8; i++) {
            int idx = tx + 256 * i;          // 2048 float4
            int r = idx >> 5;
            float4 v = make_float4(0.f, 0.f, 0.f, 0.f);
            if (r < rows_here) v = X4[idx];
            sX4[idx] = v;
        }
    }
    __syncthreads();

    const int cp = tx & 31;          // col-pair lane: pairs cp, cp+32 (cols 2cp.., 2cp+64..)
    const int r0 = (tx >> 5) * 8;

    const uint64_t* sWp = (const uint64_t*)sW;   // row k: 64 pairs at k*64 + p

    uint64_t acc[8][2];
    #pragma unroll
    for (int i = 0; i < 8; i++) { acc[i][0] = 0ull; acc[i][1] = 0ull; }

    #pragma unroll 4
    for (int k = 0; k < DIM; k++) {
        uint64_t w0 = sWp[k * 64 + cp];
        uint64_t w1 = sWp[k * 64 + cp + 32];
        const float* xk = sX + k;
        #pragma unroll
        for (int i = 0; i < 8; i++) {
            uint64_t xv = dup2(xk[(r0 + i) * DIM]);   // warp-broadcast LDS + dup
            ffma2(acc[i][0], xv, w0);
            ffma2(acc[i][1], xv, w1);
        }
    }

    // bias pairs
    float2 b0 = *(const float2*)(b + 2 * cp);
    float2 b1 = *(const float2*)(b + 2 * cp + 64);

    #pragma unroll
    for (int i = 0; i < 8; i++) {
        int r = r0 + i;
        if (r < rows_here) {
            float* hrow = g_h + (size_t)(row0 + r) * DIM;
            float2 p0 = *(float2*)&acc[i][0];
            float2 p1 = *(float2*)&acc[i][1];
            p0.x += b0.x; p0.y += b0.y;
            p1.x += b1.x; p1.y += b1.y;
            *(float2*)(hrow + 2 * cp)      = p0;
            *(float2*)(hrow + 2 * cp + 64) = p1;
        }
    }
}

// ---------------------------------------------------------------------------
// CSR build
// ---------------------------------------------------------------------------
__global__ void __launch_bounds__(256) zero_hist_kernel(int n)
{
    int i = blockIdx.x * blockDim.x + threadIdx.x;
    if (i < n) g_hist[i] = 0;
}

__global__ void __launch_bounds__(256) hist_kernel(const int* __restrict__ rows, int n_edges)
{
    int e = blockIdx.x * blockDim.x + threadIdx.x;
    if (e < n_edges) atomicAdd(&g_hist[rows[e]], 1);
}

// block-wide inclusive scan helper (1024 threads)
__device__ __forceinline__ int block_scan_incl(int v, int* wsum)
{
    int lane = threadIdx.x & 31, wid = threadIdx.x >> 5;
    int incl = v;
    #pragma unroll
    for (int o = 1; o < 32; o <<= 1) {
        int t = __shfl_up_sync(0xffffffffu, incl, o);
        if (lane >= o) incl += t;
    }
    if (lane == 31) wsum[wid] = incl;
    __syncthreads();
    if (wid == 0) {
        int w = wsum[lane];
        #pragma unroll
        for (int o = 1; o < 32; o <<= 1) {
            int t = __shfl_up_sync(0xffffffffu, w, o);
            if (lane >= o) w += t;
        }
        wsum[lane] = w;   // inclusive warp sums
    }
    __syncthreads();
    if (wid > 0) incl += wsum[wid - 1];
    return incl;
}

__global__ void __launch_bounds__(1024) scan_a_kernel(int n)
{
    __shared__ int wsum[32];
    int i = blockIdx.x * 1024 + threadIdx.x;
    int v = (i < n) ? g_hist[i] : 0;
    int incl = block_scan_incl(v, wsum);
    if (i < n) g_offsets[i] = incl - v;       // block-local exclusive
    if (threadIdx.x == 1023) g_partials[blockIdx.x] = incl;
}

__global__ void __launch_bounds__(1024) scan_b_kernel(int nb)
{
    __shared__ int wsum[32];
    int i = threadIdx.x;
    int v = (i < nb) ? g_partials[i] : 0;
    int incl = block_scan_incl(v, wsum);
    if (i < nb) g_partials[i] = incl - v;     // exclusive block offsets
}

__global__ void __launch_bounds__(1024) scan_c_kernel(int n, int n_edges)
{
    int i = blockIdx.x * 1024 + threadIdx.x;
    if (i < n) {
        int o = g_offsets[i] + g_partials[blockIdx.x];
        g_offsets[i] = o;
        g_cursor[i]  = o;
    }
    if (i == 0) g_offsets[n] = n_edges;
}

__global__ void __launch_bounds__(256) permute_kernel(
    const float* __restrict__ vals, const int* __restrict__ rows,
    const int* __restrict__ cols, int n_edges)
{
    int e = blockIdx.x * blockDim.x + threadIdx.x;
    if (e >= n_edges) return;
    int r = rows[e];
    int p = atomicAdd(&g_cursor[r], 1);
    g_edges[p] = make_uint2((unsigned)cols[e], __float_as_uint(vals[e]));
}

// ---------------------------------------------------------------------------
// Aggregate: one warp per row, register accumulation, atomic-free.
// Lane = one float4 column slice; h gather is a coalesced 512B LDG per edge.
// ---------------------------------------------------------------------------
__global__ void __launch_bounds__(256) aggregate_kernel(
    float4* __restrict__ out, int n_nodes)
{
    int gid  = blockIdx.x * blockDim.x + threadIdx.x;
    int r    = gid >> 5;
    int lane = gid & 31;
    if (r >= n_nodes) return;

    int beg = __ldg(&g_offsets[r]);
    int end = __ldg(&g_offsets[r + 1]);

    const float4* h4 = (const float4*)g_h;
    float4 acc = make_float4(0.f, 0.f, 0.f, 0.f);

    int i = beg;
    for (; i + 1 < end; i += 2) {                 // MLP=2
        uint2 e0 = __ldg(&g_edges[i]);
        uint2 e1 = __ldg(&g_edges[i + 1]);
        float4 h0 = __ldg(h4 + (size_t)e0.x * 32 + lane);
        float4 h1 = __ldg(h4 + (size_t)e1.x * 32 + lane);
        float v0 = __uint_as_float(e0.y);
        float v1 = __uint_as_float(e1.y);
        acc.x += v0 * h0.x + v1 * h1.x;
        acc.y += v0 * h0.y + v1 * h1.y;
        acc.z += v0 * h0.z + v1 * h1.z;
        acc.w += v0 * h0.w + v1 * h1.w;
    }
    if (i < end) {
        uint2 e0 = __ldg(&g_edges[i]);
        float4 h0 = __ldg(h4 + (size_t)e0.x * 32 + lane);
        float v0 = __uint_as_float(e0.y);
        acc.x += v0 * h0.x; acc.y += v0 * h0.y;
        acc.z += v0 * h0.z; acc.w += v0 * h0.w;
    }

    out[(size_t)r * 32 + lane] = acc;   // full coverage: no zero kernel needed
}

// ---------------------------------------------------------------------------
// Launch. Inputs: x, W, b, vals, rows, cols. Output: out [N,128] f32.
// ---------------------------------------------------------------------------
extern "C" void kernel_launch(void* const* d_in, const int* in_sizes, int n_in,
                              void* d_out, int out_size)
{
    const float* x    = (const float*)d_in[0];
    const float* W    = (const float*)d_in[1];
    const float* b    = (const float*)d_in[2];
    const float* vals = (const float*)d_in[3];
    const int*   rows = (const int*)d_in[4];
    const int*   cols = (const int*)d_in[5];
    float4*      out  = (float4*)d_out;

    const int n_nodes = in_sizes[0] / DIM;
    const int n_edges = in_sizes[3];

    static bool attr_set = false;
    if (!attr_set) {
        cudaFuncSetAttribute(gemm_bias_kernel,
                             cudaFuncAttributeMaxDynamicSharedMemorySize, GEMM_SMEM);
        attr_set = true;
    }

    const int nb = (n_nodes + 1023) / 1024;

    // CSR build + GEMM (sequential this round)
    zero_hist_kernel<<<(n_nodes + 255) / 256, 256>>>(n_nodes);
    gemm_bias_kernel<<<(n_nodes + 63) / 64, 256, GEMM_SMEM>>>(x, W, b, n_nodes);
    hist_kernel<<<(n_edges + 255) / 256, 256>>>(rows, n_edges);
    scan_a_kernel<<<nb, 1024>>>(n_nodes);
    scan_b_kernel<<<1, 1024>>>(nb);
    scan_c_kernel<<<nb, 1024>>>(n_nodes, n_edges);
    permute_kernel<<<(n_edges + 255) / 256, 256>>>(vals, rows, cols, n_edges);

    // atomic-free aggregation (writes every output element)
    {
        long long total_threads = (long long)n_nodes * 32;
        int blocks = (int)((total_threads + 255) / 256);
        aggregate_kernel<<<blocks, 256>>>(out, n_nodes);
    }
}

// round 4
// speedup vs baseline: 1.7997x; 1.0309x over previous
#include <cuda_runtime.h>
#include <cstdint>

#define DIM  128
#define NMAX 100000
#define EMAX 1600000

// ---- scratch (__device__ globals: allocation-free rule) ----
__device__ float g_h[(size_t)NMAX * DIM];      // h = x@W + b
__device__ uint2 g_edges[EMAX];                // row-sorted (col, val_bits)
__device__ int   g_hist[NMAX];
__device__ int   g_offsets[NMAX + 1];
__device__ int   g_cursor[NMAX];
__device__ int   g_partials[1024];

// Packed fp32 FMA (SASS FFMA2 — PTX-only form)
__device__ __forceinline__ void ffma2(uint64_t& d, uint64_t a, uint64_t b) {
    asm("fma.rn.f32x2 %0, %1, %2, %0;" : "+l"(d) : "l"(a), "l"(b));
}
__device__ __forceinline__ uint64_t dup2(float v) {
    uint64_t d; asm("mov.b64 %0, {%1, %1};" : "=l"(d) : "f"(v)); return d;
}

// ---------------------------------------------------------------------------
// GEMM: h = x@W + b. W row-major in smem (conflict-free float4 copy).
// Accumulators paired across columns: (W[k][c],W[k][c+1]) native LDS.64;
// x scalar warp-broadcast + mov.b64 dup. 256 thr, 64 rows x 128 cols/block.
// ---------------------------------------------------------------------------
#define GEMM_SMEM ((DIM * DIM + 64 * DIM) * 4)   // 96 KB

__global__ void __launch_bounds__(256, 2) gemm_bias_kernel(
    const float* __restrict__ x, const float* __restrict__ W,
    const float* __restrict__ b, int n_rows)
{
    extern __shared__ float smem[];
    float* sW = smem;             // [128][128] row-major
    float* sX = smem + DIM * DIM; // [64][128] row-major

    const int tx   = threadIdx.x;
    const int row0 = blockIdx.x * 64;
    const int rows_here = min(64, n_rows - row0);

    {
        const float4* W4 = (const float4*)W;
        float4* sW4 = (float4*)sW;
        #pragma unroll
        for (int i = 0; i < 16; i++) sW4[tx + 256 * i] = W4[tx + 256 * i];
    }
    {
        const float4* X4 = (const float4*)(x + (size_t)row0 * DIM);
        float4* sX4 = (float4*)sX;
        #pragma unroll
        for (int i = 0; i < 8; i++) {
            int idx = tx + 256 * i;
            int r = idx >> 5;
            float4 v = make_float4(0.f, 0.f, 0.f, 0.f);
            if (r < rows_here) v = X4[idx];
            sX4[idx] = v;
        }
    }
    __syncthreads();

    const int cp = tx & 31;
    const int r0 = (tx >> 5) * 8;
    const uint64_t* sWp = (const uint64_t*)sW;

    uint64_t acc[8][2];
    #pragma unroll
    for (int i = 0; i < 8; i++) { acc[i][0] = 0ull; acc[i][1] = 0ull; }

    #pragma unroll 4
    for (int k = 0; k < DIM; k++) {
        uint64_t w0 = sWp[k * 64 + cp];
        uint64_t w1 = sWp[k * 64 + cp + 32];
        const float* xk = sX + k;
        #pragma unroll
        for (int i = 0; i < 8; i++) {
            uint64_t xv = dup2(xk[(r0 + i) * DIM]);
            ffma2(acc[i][0], xv, w0);
            ffma2(acc[i][1], xv, w1);
        }
    }

    float2 b0 = *(const float2*)(b + 2 * cp);
    float2 b1 = *(const float2*)(b + 2 * cp + 64);

    #pragma unroll
    for (int i = 0; i < 8; i++) {
        int r = r0 + i;
        if (r < rows_here) {
            float* hrow = g_h + (size_t)(row0 + r) * DIM;
            float2 p0 = *(float2*)&acc[i][0];
            float2 p1 = *(float2*)&acc[i][1];
            p0.x += b0.x; p0.y += b0.y;
            p1.x += b1.x; p1.y += b1.y;
            *(float2*)(hrow + 2 * cp)      = p0;
            *(float2*)(hrow + 2 * cp + 64) = p1;
        }
    }
}

// ---------------------------------------------------------------------------
// CSR build
// ---------------------------------------------------------------------------
__global__ void __launch_bounds__(256) zero_hist_kernel(int n)
{
    int i = blockIdx.x * blockDim.x + threadIdx.x;
    if (i < n) g_hist[i] = 0;
}

__global__ void __launch_bounds__(256) hist_kernel(const int* __restrict__ rows, int n_edges)
{
    int e = blockIdx.x * blockDim.x + threadIdx.x;
    if (e < n_edges) atomicAdd(&g_hist[rows[e]], 1);
}

__device__ __forceinline__ int block_scan_incl(int v, int* wsum)
{
    int lane = threadIdx.x & 31, wid = threadIdx.x >> 5;
    int incl = v;
    #pragma unroll
    for (int o = 1; o < 32; o <<= 1) {
        int t = __shfl_up_sync(0xffffffffu, incl, o);
        if (lane >= o) incl += t;
    }
    if (lane == 31) wsum[wid] = incl;
    __syncthreads();
    if (wid == 0) {
        int w = wsum[lane];
        #pragma unroll
        for (int o = 1; o < 32; o <<= 1) {
            int t = __shfl_up_sync(0xffffffffu, w, o);
            if (lane >= o) w += t;
        }
        wsum[lane] = w;
    }
    __syncthreads();
    if (wid > 0) incl += wsum[wid - 1];
    return incl;
}

__global__ void __launch_bounds__(1024) scan_a_kernel(int n)
{
    __shared__ int wsum[32];
    int i = blockIdx.x * 1024 + threadIdx.x;
    int v = (i < n) ? g_hist[i] : 0;
    int incl = block_scan_incl(v, wsum);
    if (i < n) g_offsets[i] = incl - v;
    if (threadIdx.x == 1023) g_partials[blockIdx.x] = incl;
}

__global__ void __launch_bounds__(1024) scan_b_kernel(int nb)
{
    __shared__ int wsum[32];
    int i = threadIdx.x;
    int v = (i < nb) ? g_partials[i] : 0;
    int incl = block_scan_incl(v, wsum);
    if (i < nb) g_partials[i] = incl - v;
}

__global__ void __launch_bounds__(1024) scan_c_kernel(int n, int n_edges)
{
    int i = blockIdx.x * 1024 + threadIdx.x;
    if (i < n) {
        int o = g_offsets[i] + g_partials[blockIdx.x];
        g_offsets[i] = o;
        g_cursor[i]  = o;
    }
    if (i == 0) g_offsets[n] = n_edges;
}

__global__ void __launch_bounds__(256) permute_kernel(
    const float* __restrict__ vals, const int* __restrict__ rows,
    const int* __restrict__ cols, int n_edges)
{
    int e = blockIdx.x * blockDim.x + threadIdx.x;
    if (e >= n_edges) return;
    int r = rows[e];
    int p = atomicAdd(&g_cursor[r], 1);
    g_edges[p] = make_uint2((unsigned)cols[e], __float_as_uint(vals[e]));
}

// ---------------------------------------------------------------------------
// Aggregate: one warp per row, register accumulation, atomic-free, MLP=4.
// ---------------------------------------------------------------------------
__global__ void __launch_bounds__(256) aggregate_kernel(
    float4* __restrict__ out, int n_nodes)
{
    int gid  = blockIdx.x * blockDim.x + threadIdx.x;
    int r    = gid >> 5;
    int lane = gid & 31;
    if (r >= n_nodes) return;

    int beg = __ldg(&g_offsets[r]);
    int end = __ldg(&g_offsets[r + 1]);

    const float4* h4 = (const float4*)g_h;
    float4 acc = make_float4(0.f, 0.f, 0.f, 0.f);

    int i = beg;
    for (; i + 3 < end; i += 4) {                 // MLP=4 on the h gather
        uint2 e0 = __ldg(&g_edges[i]);
        uint2 e1 = __ldg(&g_edges[i + 1]);
        uint2 e2 = __ldg(&g_edges[i + 2]);
        uint2 e3 = __ldg(&g_edges[i + 3]);
        float4 h0 = __ldg(h4 + (size_t)e0.x * 32 + lane);
        float4 h1 = __ldg(h4 + (size_t)e1.x * 32 + lane);
        float4 h2 = __ldg(h4 + (size_t)e2.x * 32 + lane);
        float4 h3 = __ldg(h4 + (size_t)e3.x * 32 + lane);
        float v0 = __uint_as_float(e0.y);
        float v1 = __uint_as_float(e1.y);
        float v2 = __uint_as_float(e2.y);
        float v3 = __uint_as_float(e3.y);
        acc.x += v0 * h0.x + v1 * h1.x + v2 * h2.x + v3 * h3.x;
        acc.y += v0 * h0.y + v1 * h1.y + v2 * h2.y + v3 * h3.y;
        acc.z += v0 * h0.z + v1 * h1.z + v2 * h2.z + v3 * h3.z;
        acc.w += v0 * h0.w + v1 * h1.w + v2 * h2.w + v3 * h3.w;
    }
    for (; i < end; i++) {
        uint2 e0 = __ldg(&g_edges[i]);
        float4 h0 = __ldg(h4 + (size_t)e0.x * 32 + lane);
        float v0 = __uint_as_float(e0.y);
        acc.x += v0 * h0.x; acc.y += v0 * h0.y;
        acc.z += v0 * h0.z; acc.w += v0 * h0.w;
    }

    out[(size_t)r * 32 + lane] = acc;
}

// ---------------------------------------------------------------------------
// Launch. Two-branch graph:
//   branch A (stream 0): GEMM
//   branch B (stream sB): zero_hist -> hist -> scan x3 -> permute
//   join -> aggregate
// Streams/events created once on the (uncaptured) correctness call.
// ---------------------------------------------------------------------------
extern "C" void kernel_launch(void* const* d_in, const int* in_sizes, int n_in,
                              void* d_out, int out_size)
{
    const float* x    = (const float*)d_in[0];
    const float* W    = (const float*)d_in[1];
    const float* b    = (const float*)d_in[2];
    const float* vals = (const float*)d_in[3];
    const int*   rows = (const int*)d_in[4];
    const int*   cols = (const int*)d_in[5];
    float4*      out  = (float4*)d_out;

    const int n_nodes = in_sizes[0] / DIM;
    const int n_edges = in_sizes[3];

    static cudaStream_t sB;
    static cudaEvent_t  evFork, evJoin;
    static bool init = false;
    if (!init) {
        cudaFuncSetAttribute(gemm_bias_kernel,
                             cudaFuncAttributeMaxDynamicSharedMemorySize, GEMM_SMEM);
        cudaStreamCreateWithFlags(&sB, cudaStreamNonBlocking);
        cudaEventCreateWithFlags(&evFork, cudaEventDisableTiming);
        cudaEventCreateWithFlags(&evJoin, cudaEventDisableTiming);
        init = true;
    }

    const int nb = (n_nodes + 1023) / 1024;

    // fork
    cudaEventRecord(evFork, 0);
    cudaStreamWaitEvent(sB, evFork, 0);

    // branch B: CSR build (rows/cols/vals only)
    zero_hist_kernel<<<(n_nodes + 255) / 256, 256, 0, sB>>>(n_nodes);
    hist_kernel<<<(n_edges + 255) / 256, 256, 0, sB>>>(rows, n_edges);
    scan_a_kernel<<<nb, 1024, 0, sB>>>(n_nodes);
    scan_b_kernel<<<1, 1024, 0, sB>>>(nb);
    scan_c_kernel<<<nb, 1024, 0, sB>>>(n_nodes, n_edges);
    permute_kernel<<<(n_edges + 255) / 256, 256, 0, sB>>>(vals, rows, cols, n_edges);

    // branch A: GEMM on stream 0
    gemm_bias_kernel<<<(n_nodes + 63) / 64, 256, GEMM_SMEM>>>(x, W, b, n_nodes);

    // join
    cudaEventRecord(evJoin, sB);
    cudaStreamWaitEvent(0, evJoin, 0);

    // aggregate (needs both branches)
    {
        long long total_threads = (long long)n_nodes * 32;
        int blocks = (int)((total_threads + 255) / 256);
        aggregate_kernel<<<blocks, 256>>>(out, n_nodes);
    }
}